// round 14
// baseline (speedup 1.0000x reference)
#include <cuda_runtime.h>
#include <cuda_bf16.h>

// out[n,c,k,l] = x[n,c,oh,ow] - xpad[n,c,oh+i,ow+j]; K=7, PAD=3
// x:(16,64,56,56) f32 -> out:(16,64,49,3136) f32.
//
// R13b: STG.256 experiment. Same shape as the 95.9us best (1024x256, .cs,
// fused staging, one barrier), but 8-pixel groups: 49 st.global.cs.v8.f32
// per group (sm_100+ 256-bit stores) -> half the store instructions, 1024B
// contiguous burst per warp-store. Tests whether wider bursts improve
// LTS/DRAM write efficiency. 32B alignment: plane stride 12544%32==0, l%8==0.

#define PLANE   3136        // 56*56
#define TPITCH  64          // padded pitch (16B-aligned rows)
#define TROWS   62          // 56 + 2*3
#define NTHREADS 256
#define NGROUPS8 392        // 3136 / 8 groups per k

__device__ __forceinline__ void stcs_v8(float* p, const float o[8]) {
    asm volatile(
        "st.global.cs.v8.f32 [%0], {%1, %2, %3, %4, %5, %6, %7, %8};"
        :: "l"(p),
           "f"(o[0]), "f"(o[1]), "f"(o[2]), "f"(o[3]),
           "f"(o[4]), "f"(o[5]), "f"(o[6]), "f"(o[7])
        : "memory");
}

__global__ __launch_bounds__(NTHREADS, 1)
void Subtraction_68212670595965_kernel(const float* __restrict__ x,
                                       float* __restrict__ out) {
    __shared__ float tile[TROWS * TPITCH];   // 62*64*4 = 15872 B

    const int nc = blockIdx.x;               // n*64 + c, 0..1023
    const float* __restrict__ xin = x + (size_t)nc * PLANE;
    float* __restrict__ outb = out + (size_t)nc * 49 * PLANE;

    const int tid = threadIdx.x;

    // ---- Fused staging: halo zeros + interior vector loads, ONE barrier ----
    {
        float4 z = {0.f, 0.f, 0.f, 0.f};
        // top rows 0..2 and bottom rows 59..61 (each 64 floats = 16 float4)
        if (tid < 96) {
            const int half = tid / 48;               // 0=top, 1=bottom
            const int q    = tid - half * 48;        // 0..47
            const int row  = half ? (59 + q / 16) : (q / 16);
            reinterpret_cast<float4*>(&tile[row * TPITCH])[q & 15] = z;
        }
        // side halos: 56 rows * 8 cols (0..2, 59..63) = 448 scalars
        #pragma unroll 1
        for (int s = tid; s < 448; s += NTHREADS) {
            const int r  = s / 8;
            const int cc = s & 7;
            const int col = (cc < 3) ? cc : (56 + cc);
            tile[(r + 3) * TPITCH + col] = 0.0f;
        }
    }

    // interior fill: 56 rows x 14 float4 LDG.128, scattered STS (+3 halo).
    #pragma unroll 1
    for (int idx = tid; idx < 56 * 14; idx += NTHREADS) {
        const int r  = idx / 14;          // input row 0..55
        const int c4 = idx - r * 14;      // float4 index within row
        const float4 v = reinterpret_cast<const float4*>(xin + r * 56)[c4];
        float* dst = &tile[(r + 3) * TPITCH + 3 + c4 * 4];
        dst[0] = v.x; dst[1] = v.y; dst[2] = v.z; dst[3] = v.w;
    }
    __syncthreads();

    // ---- Store phase: 8-pixel groups, 49 STG.256 per group ----
    #pragma unroll 1
    for (int g = tid; g < NGROUPS8; g += NTHREADS) {
        const int oh  = g / 7;
        const int ow8 = (g - oh * 7) * 8;           // 0,8,...,48

        // centers: tile[(oh+3)][ow8+3 .. ow8+10]
        float c[8];
        #pragma unroll
        for (int t = 0; t < 8; ++t)
            c[t] = tile[(oh + 3) * TPITCH + ow8 + 3 + t];

        float* __restrict__ op = outb + oh * 56 + ow8;

        #pragma unroll
        for (int i = 0; i < 7; ++i) {
            // window: tile[(oh+i)][ow8 .. ow8+14] -> 16 floats via 4x LDS.128
            const float4* rp =
                reinterpret_cast<const float4*>(&tile[(oh + i) * TPITCH + ow8]);
            const float4 a = rp[0];
            const float4 b = rp[1];
            const float4 d = rp[2];
            const float4 e = rp[3];
            const float w[15] = {a.x, a.y, a.z, a.w,
                                 b.x, b.y, b.z, b.w,
                                 d.x, d.y, d.z, d.w,
                                 e.x, e.y, e.z};
            #pragma unroll
            for (int j = 0; j < 7; ++j) {
                float o[8];
                #pragma unroll
                for (int t = 0; t < 8; ++t)
                    o[t] = c[t] - w[j + t];
                stcs_v8(op + (i * 7 + j) * PLANE, o);
            }
        }
    }
}

extern "C" void kernel_launch(void* const* d_in, const int* in_sizes, int n_in,
                              void* d_out, int out_size) {
    const float* x = (const float*)d_in[0];
    float* out = (float*)d_out;
    Subtraction_68212670595965_kernel<<<1024, NTHREADS>>>(x, out);
}

// round 15
// speedup vs baseline: 1.0638x; 1.0638x over previous
#include <cuda_runtime.h>
#include <cuda_bf16.h>

// out[n,c,k,l] = x[n,c,oh,ow] - xpad[n,c,oh+i,ow+j]; K=7, PAD=3
// x:(16,64,56,56) f32 -> out:(16,64,49,3136) f32.
//
// FINAL — best measured 95.9us, DRAM-write-bound at ~6.7 TB/s effective
// (HBM3e write-turnaround ceiling for a pure store stream).
//
// Exhaustive lever verdicts (isolated, measured):
//   store width:  STG.32 < STG.128 (BEST) > STG.256 (regs 94, occ 20% — R14)
//   cache policy: .cs streaming (BEST) > .wb (+4.7us — R12)
//   concurrency:  2/SM bad, 4/SM x 256thr BEST, 5/SM bad (R3), 8x128 bad (R9)
//   staging:      fused 1-barrier BEST (R6); reg-prefetch neutral (R8)
//   bytes:        irreducible; issue 7.9%, fma 4.5% — never binding.
//
// Shape: 1024 CTAs (one per (n,c) plane) x 256 threads, 4 resident CTAs/SM.
// 62x64 padded SMEM tile; halo-zero fused with LDG.128 staging, one barrier;
// 49 st.global.cs.v4 per 4-pixel group, perfectly coalesced per warp.

#define PLANE   3136        // 56*56
#define TPITCH  64          // padded pitch (16B-aligned rows)
#define TROWS   62          // 56 + 2*3
#define NTHREADS 256
#define NGROUPS 784         // 3136 / 4 float4-groups per k

__global__ __launch_bounds__(NTHREADS, 1)
void Subtraction_68212670595965_kernel(const float* __restrict__ x,
                                       float* __restrict__ out) {
    __shared__ float tile[TROWS * TPITCH];   // 62*64*4 = 15872 B

    const int nc = blockIdx.x;               // n*64 + c, 0..1023
    const float* __restrict__ xin = x + (size_t)nc * PLANE;
    float* __restrict__ outb = out + (size_t)nc * 49 * PLANE;

    const int tid = threadIdx.x;

    // ---- Fused staging: halo zeros + interior vector loads, ONE barrier ----
    {
        float4 z = {0.f, 0.f, 0.f, 0.f};
        // top rows 0..2 and bottom rows 59..61 (each 64 floats = 16 float4)
        if (tid < 96) {
            const int half = tid / 48;               // 0=top, 1=bottom
            const int q    = tid - half * 48;        // 0..47
            const int row  = half ? (59 + q / 16) : (q / 16);
            reinterpret_cast<float4*>(&tile[row * TPITCH])[q & 15] = z;
        }
        // side halos: 56 rows * 8 cols (0..2, 59..63) = 448 scalars
        #pragma unroll 1
        for (int s = tid; s < 448; s += NTHREADS) {
            const int r  = s / 8;
            const int cc = s & 7;
            const int col = (cc < 3) ? cc : (56 + cc);
            tile[(r + 3) * TPITCH + col] = 0.0f;
        }
    }

    // interior fill: 56 rows x 14 float4 LDG.128, scattered STS (+3 halo).
    #pragma unroll 1
    for (int idx = tid; idx < 56 * 14; idx += NTHREADS) {
        const int r  = idx / 14;          // input row 0..55
        const int c4 = idx - r * 14;      // float4 index within row
        const float4 v = reinterpret_cast<const float4*>(xin + r * 56)[c4];
        float* dst = &tile[(r + 3) * TPITCH + 3 + c4 * 4];
        dst[0] = v.x; dst[1] = v.y; dst[2] = v.z; dst[3] = v.w;
    }
    __syncthreads();

    // ---- Store phase: 49 streaming STG.128 per 4-pixel group ----
    #pragma unroll 1
    for (int g = tid; g < NGROUPS; g += NTHREADS) {
        const int oh  = g / 14;
        const int ow4 = (g - oh * 14) * 4;          // 0,4,...,52

        const int cbase = (oh + 3) * TPITCH + ow4 + 3;
        const float c0 = tile[cbase + 0];
        const float c1 = tile[cbase + 1];
        const float c2 = tile[cbase + 2];
        const float c3 = tile[cbase + 3];

        float* __restrict__ op = outb + 4 * g;

        #pragma unroll
        for (int i = 0; i < 7; ++i) {
            const float4* rp =
                reinterpret_cast<const float4*>(&tile[(oh + i) * TPITCH + ow4]);
            const float4 a = rp[0];
            const float4 b = rp[1];
            const float4 cq = rp[2];
            const float r[12] = {a.x, a.y, a.z, a.w,
                                 b.x, b.y, b.z, b.w,
                                 cq.x, cq.y, cq.z, cq.w};
            #pragma unroll
            for (int j = 0; j < 7; ++j) {
                float4 o;
                o.x = c0 - r[j + 0];
                o.y = c1 - r[j + 1];
                o.z = c2 - r[j + 2];
                o.w = c3 - r[j + 3];
                __stcs(reinterpret_cast<float4*>(op + (i * 7 + j) * PLANE), o);
            }
        }
    }
}

extern "C" void kernel_launch(void* const* d_in, const int* in_sizes, int n_in,
                              void* d_out, int out_size) {
    const float* x = (const float*)d_in[0];
    float* out = (float*)d_out;
    Subtraction_68212670595965_kernel<<<1024, NTHREADS>>>(x, out);
}